// round 1
// baseline (speedup 1.0000x reference)
#include <cuda_runtime.h>
#include <cstdint>

// ---------------- problem constants ----------------
#define BATCH 32
#define N1 4096
#define S1 512
#define G1 32
#define S2 128
#define G2 64

// ---------------- scratch (device globals; no cudaMalloc allowed) ----------------
__device__ float g_bufA[36u * 1024u * 1024u];   // up to (524288,64) or (262144,131)
__device__ float g_bufB[68u * 1024u * 1024u];   // up to (524288,128) or (262144,256)
__device__ float g_cent1[BATCH * S1 * 3];
__device__ float g_cent2[BATCH * S2 * 3];
__device__ int   g_idx1[BATCH * S1];
__device__ int   g_idx2[BATCH * S2];
__device__ float g_l1p[BATCH * S1 * 128];
__device__ float g_l2p[BATCH * S2 * 256];
__device__ float g_feat[BATCH * 1024];

// squared distance with NO fma contraction, same assoc order as jnp.sum over last axis
__device__ __forceinline__ float sqd(float dx, float dy, float dz) {
    return __fadd_rn(__fadd_rn(__fmul_rn(dx, dx), __fmul_rn(dy, dy)), __fmul_rn(dz, dz));
}

// ---------------- FPS: one block per batch, points in registers ----------------
// pts layout generic: coord(i,c) = base[i*sp + c*sc]; base = pts + b*strideB
template <int PPT>
__global__ void fps_kernel(const float* __restrict__ pts, int N, int S,
                           long strideB, int sp, int sc,
                           int* __restrict__ outIdx, float* __restrict__ outXyz) {
    const int T = 512;
    int b = blockIdx.x;
    int t = threadIdx.x;
    const float* base = pts + (size_t)b * strideB;

    float px[PPT], py[PPT], pz[PPT], dist[PPT];
#pragma unroll
    for (int j = 0; j < PPT; j++) {
        int i = t + j * T;
        px[j] = base[(size_t)i * sp];
        py[j] = base[(size_t)i * sp + sc];
        pz[j] = base[(size_t)i * sp + 2 * (size_t)sc];
        dist[j] = 1e10f;
    }

    __shared__ float s_c[3];
    __shared__ float s_v[16];
    __shared__ int   s_i[16];
    __shared__ int   s_far;

    if (t == 0) {
        s_far = 0;
        outIdx[(size_t)b * S] = 0;
        s_c[0] = px[0]; s_c[1] = py[0]; s_c[2] = pz[0];
        float* ox = outXyz + ((size_t)b * S) * 3;
        ox[0] = px[0]; ox[1] = py[0]; ox[2] = pz[0];
    }
    __syncthreads();

    for (int it = 0; it < S - 1; it++) {
        float cx = s_c[0], cy = s_c[1], cz = s_c[2];
        float bestv = -1.0f;
        int   besti = 0x7fffffff;
#pragma unroll
        for (int j = 0; j < PPT; j++) {
            float d = sqd(px[j] - cx, py[j] - cy, pz[j] - cz);
            float nd = fminf(dist[j], d);
            dist[j] = nd;
            if (nd > bestv) { bestv = nd; besti = t + j * T; }   // ascending j -> keeps smallest idx
        }
        // warp reduce (max value, tie -> smaller index == argmax first occurrence)
#pragma unroll
        for (int off = 16; off; off >>= 1) {
            float ov = __shfl_down_sync(0xffffffffu, bestv, off);
            int   oi = __shfl_down_sync(0xffffffffu, besti, off);
            if (ov > bestv || (ov == bestv && oi < besti)) { bestv = ov; besti = oi; }
        }
        if ((t & 31) == 0) { s_v[t >> 5] = bestv; s_i[t >> 5] = besti; }
        __syncthreads();
        if (t < 32) {
            float v = (t < 16) ? s_v[t] : -1.0f;
            int   ii = (t < 16) ? s_i[t] : 0x7fffffff;
#pragma unroll
            for (int off = 16; off; off >>= 1) {
                float ov = __shfl_down_sync(0xffffffffu, v, off);
                int   oi = __shfl_down_sync(0xffffffffu, ii, off);
                if (ov > v || (ov == v && oi < ii)) { v = ov; ii = oi; }
            }
            if (t == 0) s_far = ii;
        }
        __syncthreads();
        int far = s_far;
        if (t == (far & (T - 1))) {
            int j = far >> 9;  // T = 512
            s_c[0] = px[j]; s_c[1] = py[j]; s_c[2] = pz[j];
            outIdx[(size_t)b * S + it + 1] = far;
            float* ox = outXyz + ((size_t)b * S + it + 1) * 3;
            ox[0] = px[j]; ox[1] = py[j]; ox[2] = pz[j];
        }
        __syncthreads();
    }
}

// ---------------- ball query + grouping, SA1 (xyz only, K=3 rows) ----------------
__global__ void bq_group1(const float* __restrict__ xyz,   // (B,3,N1)
                          const float* __restrict__ cent,  // (B,S1,3)
                          float* __restrict__ out) {       // (B*S1*G1, 3)
    extern __shared__ float sm[];
    float* sx = sm; float* sy = sm + N1; float* sz = sm + 2 * N1;
    __shared__ int sel[8][G1];
    int b = blockIdx.x;
    const float* base = xyz + (size_t)b * 3 * N1;
    for (int i = threadIdx.x; i < N1; i += blockDim.x) {
        sx[i] = base[i]; sy[i] = base[N1 + i]; sz[i] = base[2 * N1 + i];
    }
    __syncthreads();
    const float R2 = (float)(0.2 * 0.2);   // double-math constant, matches JAX promotion
    int warp = threadIdx.x >> 5, lane = threadIdx.x & 31;
    for (int s = blockIdx.y * 8 + warp; s < S1; s += gridDim.y * 8) {
        const float* cc = cent + ((size_t)b * S1 + s) * 3;
        float cx = cc[0], cy = cc[1], cz = cc[2];
        int cnt = 0, first = -1;
        for (int bi = 0; bi < N1; bi += 32) {
            int i = bi + lane;
            float d = sqd(sx[i] - cx, sy[i] - cy, sz[i] - cz);
            bool ok = (d <= R2);
            unsigned m = __ballot_sync(0xffffffffu, ok);
            if (m) {
                if (first < 0) first = bi + __ffs(m) - 1;
                int pos = cnt + __popc(m & ((1u << lane) - 1u));
                if (ok && pos < G1) sel[warp][pos] = i;
                cnt += __popc(m);
                if (cnt >= G1) break;
            }
        }
        for (int p = cnt + lane; p < G1; p += 32) sel[warp][p] = first;
        __syncwarp();
        int i = sel[warp][lane];
        size_t row = (((size_t)(b * S1 + s)) * G1 + lane) * 3;
        out[row + 0] = sx[i] - cx;
        out[row + 1] = sy[i] - cy;
        out[row + 2] = sz[i] - cz;
        __syncwarp();
    }
}

// ---------------- ball query + grouping, SA2 (xyz rel + 128 feats, K=131 rows) -----
__global__ void bq_group2(const float* __restrict__ pts,   // (B,512,3) = cent1
                          const float* __restrict__ cent,  // (B,128,3) = cent2
                          const float* __restrict__ feat,  // (B,512,128) = l1p
                          float* __restrict__ out) {       // (B*S2*G2, 131)
    __shared__ float sx[512], sy[512], sz[512];
    __shared__ int sel[8][G2];
    int b = blockIdx.x;
    const float* base = pts + (size_t)b * 512 * 3;
    for (int i = threadIdx.x; i < 512; i += blockDim.x) {
        sx[i] = base[i * 3]; sy[i] = base[i * 3 + 1]; sz[i] = base[i * 3 + 2];
    }
    __syncthreads();
    const float R2 = (float)(0.4 * 0.4);
    int warp = threadIdx.x >> 5, lane = threadIdx.x & 31;
    for (int s = blockIdx.y * 8 + warp; s < S2; s += gridDim.y * 8) {
        const float* cc = cent + ((size_t)b * S2 + s) * 3;
        float cx = cc[0], cy = cc[1], cz = cc[2];
        int cnt = 0, first = -1;
        for (int bi = 0; bi < 512; bi += 32) {
            int i = bi + lane;
            float d = sqd(sx[i] - cx, sy[i] - cy, sz[i] - cz);
            bool ok = (d <= R2);
            unsigned m = __ballot_sync(0xffffffffu, ok);
            if (m) {
                if (first < 0) first = bi + __ffs(m) - 1;
                int pos = cnt + __popc(m & ((1u << lane) - 1u));
                if (ok && pos < G2) sel[warp][pos] = i;
                cnt += __popc(m);
                if (cnt >= G2) break;
            }
        }
        for (int p = cnt + lane; p < G2; p += 32) sel[warp][p] = first;
        __syncwarp();
        for (int n = 0; n < G2; n++) {
            int i = sel[warp][n];
            float* row = out + ((((size_t)(b * S2 + s)) * G2) + n) * 131;
            if (lane == 0) {
                row[0] = sx[i] - cx; row[1] = sy[i] - cy; row[2] = sz[i] - cz;
            }
            const float* f = feat + ((size_t)(b * 512) + i) * 128;
            for (int c = lane; c < 128; c += 32) row[3 + c] = f[c];
        }
        __syncwarp();
    }
}

// ---------------- dedicated K=3 layer (memory bound) ----------------
__global__ void mlp_k3(const float* __restrict__ A, const float* __restrict__ W,
                       const float* __restrict__ bias, float* __restrict__ C, int M) {
    __shared__ float w[192], bb[64];
    if (threadIdx.x < 192) w[threadIdx.x] = W[threadIdx.x];
    if (threadIdx.x < 64) bb[threadIdx.x] = bias[threadIdx.x];
    __syncthreads();
    int gid = blockIdx.x * blockDim.x + threadIdx.x;
    int m = gid >> 6, o = gid & 63;
    if (m >= M) return;
    float a0 = A[(size_t)m * 3 + 0], a1 = A[(size_t)m * 3 + 1], a2 = A[(size_t)m * 3 + 2];
    float v = bb[o] + a0 * w[o * 3 + 0] + a1 * w[o * 3 + 1] + a2 * w[o * 3 + 2];
    C[(size_t)gid] = fmaxf(v, 0.0f);
}

// ---------------- generic fp32 GEMM: C = act(A(M,K) * W(N,K)^T + bias) ----------------
#define BM 128
#define BN 64
#define BK 16
__global__ void gemm_bias_act(const float* __restrict__ A, const float* __restrict__ W,
                              const float* __restrict__ bias, float* __restrict__ C,
                              int M, int K, int N, int doRelu) {
    __shared__ float As[BK][BM + 4];
    __shared__ float Ws[BK][BN];
    int bm = blockIdx.x * BM, bn = blockIdx.y * BN;
    int tid = threadIdx.x;                  // 256 threads
    int tx = tid & 15, ty = tid >> 4;       // tx: N dir (x4), ty: M dir (x8)
    float acc[8][4] = {};

    for (int k0 = 0; k0 < K; k0 += BK) {
        int lr = tid >> 1, lk0 = (tid & 1) * 8;
        int gm = bm + lr;
#pragma unroll
        for (int i = 0; i < 8; i++) {
            int kk = k0 + lk0 + i;
            As[lk0 + i][lr] = (gm < M && kk < K) ? A[(size_t)gm * K + kk] : 0.0f;
        }
        int ln = tid >> 2, lkw = (tid & 3) * 4;
        int gn = bn + ln;
#pragma unroll
        for (int i = 0; i < 4; i++) {
            int kk = k0 + lkw + i;
            Ws[lkw + i][ln] = (gn < N && kk < K) ? W[(size_t)gn * K + kk] : 0.0f;
        }
        __syncthreads();
#pragma unroll
        for (int k = 0; k < BK; k++) {
            float a[8], bvv[4];
#pragma unroll
            for (int i = 0; i < 8; i++) a[i] = As[k][ty * 8 + i];
#pragma unroll
            for (int j = 0; j < 4; j++) bvv[j] = Ws[k][tx * 4 + j];
#pragma unroll
            for (int i = 0; i < 8; i++)
#pragma unroll
                for (int j = 0; j < 4; j++) acc[i][j] += a[i] * bvv[j];
        }
        __syncthreads();
    }
#pragma unroll
    for (int j = 0; j < 4; j++) {
        int gn = bn + tx * 4 + j;
        if (gn >= N) continue;
        float bv = bias[gn];
#pragma unroll
        for (int i = 0; i < 8; i++) {
            int gm = bm + ty * 8 + i;
            if (gm < M) {
                float v = acc[i][j] + bv;
                if (doRelu) v = fmaxf(v, 0.0f);
                C[(size_t)gm * N + gn] = v;
            }
        }
    }
}

// ---------------- max pool over group dim: in (S*G, C) -> out (S, C) ----------------
__global__ void maxpool_kernel(const float* __restrict__ in, float* __restrict__ out,
                               int S, int G, int C) {
    int idx = blockIdx.x * blockDim.x + threadIdx.x;
    if (idx >= S * C) return;
    int s = idx / C, c = idx - s * C;
    const float* p = in + ((size_t)s * G) * C + c;
    float v = p[0];
    for (int g = 1; g < G; g++) v = fmaxf(v, p[(size_t)g * C]);
    out[idx] = v;
}

// ---------------- SA3 concat: rows (B*S2, 259) = [cent2(3) | l2p(256)] ----------------
__global__ void concat_sa3(const float* __restrict__ cent2, const float* __restrict__ l2p,
                           float* __restrict__ out) {
    int idx = blockIdx.x * blockDim.x + threadIdx.x;
    const int TOT = BATCH * S2 * 259;
    if (idx >= TOT) return;
    int r = idx / 259, c = idx - r * 259;
    out[idx] = (c < 3) ? cent2[r * 3 + c] : l2p[(size_t)r * 256 + (c - 3)];
}

// ---------------- orchestration ----------------
static inline void launch_gemm(const float* A, const float* W, const float* bias, float* C,
                               int M, int K, int N, int relu) {
    dim3 grid((M + BM - 1) / BM, (N + BN - 1) / BN);
    gemm_bias_act<<<grid, 256>>>(A, W, bias, C, M, K, N, relu);
}

extern "C" void kernel_launch(void* const* d_in, const int* in_sizes, int n_in,
                              void* d_out, int out_size) {
    (void)in_sizes; (void)n_in; (void)out_size;
    const float* xyz  = (const float*)d_in[0];
    const float* s1w0 = (const float*)d_in[1];  const float* s1b0 = (const float*)d_in[2];
    const float* s1w1 = (const float*)d_in[3];  const float* s1b1 = (const float*)d_in[4];
    const float* s1w2 = (const float*)d_in[5];  const float* s1b2 = (const float*)d_in[6];
    const float* s2w0 = (const float*)d_in[7];  const float* s2b0 = (const float*)d_in[8];
    const float* s2w1 = (const float*)d_in[9];  const float* s2b1 = (const float*)d_in[10];
    const float* s2w2 = (const float*)d_in[11]; const float* s2b2 = (const float*)d_in[12];
    const float* s3w0 = (const float*)d_in[13]; const float* s3b0 = (const float*)d_in[14];
    const float* s3w1 = (const float*)d_in[15]; const float* s3b1 = (const float*)d_in[16];
    const float* s3w2 = (const float*)d_in[17]; const float* s3b2 = (const float*)d_in[18];
    const float* f1w  = (const float*)d_in[19]; const float* f1b  = (const float*)d_in[20];
    const float* f2w  = (const float*)d_in[21]; const float* f2b  = (const float*)d_in[22];
    const float* f3w  = (const float*)d_in[23]; const float* f3b  = (const float*)d_in[24];
    float* out = (float*)d_out;

    float *bufA, *bufB, *cent1, *cent2, *l1p, *l2p, *featv;
    int *idx1, *idx2;
    cudaGetSymbolAddress((void**)&bufA, g_bufA);
    cudaGetSymbolAddress((void**)&bufB, g_bufB);
    cudaGetSymbolAddress((void**)&cent1, g_cent1);
    cudaGetSymbolAddress((void**)&cent2, g_cent2);
    cudaGetSymbolAddress((void**)&l1p, g_l1p);
    cudaGetSymbolAddress((void**)&l2p, g_l2p);
    cudaGetSymbolAddress((void**)&featv, g_feat);
    cudaGetSymbolAddress((void**)&idx1, g_idx1);
    cudaGetSymbolAddress((void**)&idx2, g_idx2);

    cudaFuncSetAttribute(bq_group1, cudaFuncAttributeMaxDynamicSharedMemorySize, 3 * N1 * 4);

    const int M1 = BATCH * S1 * G1;   // 524288
    const int M2 = BATCH * S2 * G2;   // 262144
    const int M3 = BATCH * S2;        // 4096

    // ---- SA1 ----
    fps_kernel<8><<<BATCH, 512>>>(xyz, N1, S1, (long)3 * N1, 1, N1, idx1, cent1);
    bq_group1<<<dim3(BATCH, 8), 256, 3 * N1 * 4>>>(xyz, cent1, bufA);
    mlp_k3<<<(M1 * 64) / 256, 256>>>(bufA, s1w0, s1b0, bufB, M1);
    launch_gemm(bufB, s1w1, s1b1, bufA, M1, 64, 64, 1);
    launch_gemm(bufA, s1w2, s1b2, bufB, M1, 64, 128, 1);
    maxpool_kernel<<<(BATCH * S1 * 128 + 255) / 256, 256>>>(bufB, l1p, BATCH * S1, G1, 128);

    // ---- SA2 ----
    fps_kernel<1><<<BATCH, 512>>>(cent1, S1, S2, (long)S1 * 3, 3, 1, idx2, cent2);
    bq_group2<<<dim3(BATCH, 2), 256>>>(cent1, cent2, l1p, bufA);
    launch_gemm(bufA, s2w0, s2b0, bufB, M2, 131, 128, 1);
    launch_gemm(bufB, s2w1, s2b1, bufA, M2, 128, 128, 1);
    launch_gemm(bufA, s2w2, s2b2, bufB, M2, 128, 256, 1);
    maxpool_kernel<<<(BATCH * S2 * 256 + 255) / 256, 256>>>(bufB, l2p, BATCH * S2, G2, 256);

    // ---- SA3 (group all) ----
    concat_sa3<<<(M3 * 259 + 255) / 256, 256>>>(cent2, l2p, bufA);
    launch_gemm(bufA, s3w0, s3b0, bufB, M3, 259, 256, 1);
    launch_gemm(bufB, s3w1, s3b1, bufA, M3, 256, 512, 1);
    launch_gemm(bufA, s3w2, s3b2, bufB, M3, 512, 1024, 1);
    maxpool_kernel<<<(BATCH * 1024 + 255) / 256, 256>>>(bufB, featv, BATCH, S2, 1024);

    // ---- head ----
    launch_gemm(featv, f1w, f1b, bufA, BATCH, 1024, 512, 1);
    launch_gemm(bufA, f2w, f2b, bufB, BATCH, 512, 256, 1);
    launch_gemm(bufB, f3w, f3b, out, BATCH, 256, 6, 0);
}

// round 3
// speedup vs baseline: 1.6197x; 1.6197x over previous
#include <cuda_runtime.h>
#include <cuda_bf16.h>
#include <cstdint>

// ---------------- problem constants ----------------
#define BATCH 32
#define N1 4096
#define S1 512
#define G1 32
#define S2 128
#define G2 64

// ---------------- scratch (device globals; no cudaMalloc allowed) ----------------
__device__ float g_bufA[36u * 1024u * 1024u];
__device__ float g_bufB[68u * 1024u * 1024u];
__device__ float g_cent1[BATCH * S1 * 3];
__device__ float g_cent2[BATCH * S2 * 3];
__device__ int   g_idx1[BATCH * S1];
__device__ int   g_idx2[BATCH * S2];
__device__ float g_l1p[BATCH * S1 * 128];
__device__ float g_l2p[BATCH * S2 * 256];
__device__ float g_feat[BATCH * 1024];

// squared distance with NO fma contraction, same assoc order as jnp.sum over last axis
__device__ __forceinline__ float sqd(float dx, float dy, float dz) {
    return __fadd_rn(__fadd_rn(__fmul_rn(dx, dx), __fmul_rn(dy, dy)), __fmul_rn(dz, dz));
}

// ================= mma.sync helpers (base PTX, works on compute_103) =================
__device__ __forceinline__ uint32_t smem_u32(const void* p) {
    uint32_t a;
    asm("{ .reg .u64 t; cvta.to.shared.u64 t, %1; cvt.u32.u64 %0, t; }" : "=r"(a) : "l"(p));
    return a;
}
__device__ __forceinline__ void ldm_x4(uint32_t addr, uint32_t& r0, uint32_t& r1,
                                       uint32_t& r2, uint32_t& r3) {
    asm volatile("ldmatrix.sync.aligned.m8n8.x4.shared.b16 {%0,%1,%2,%3}, [%4];"
                 : "=r"(r0), "=r"(r1), "=r"(r2), "=r"(r3) : "r"(addr));
}
__device__ __forceinline__ void mma_bf16(float* c, uint32_t a0, uint32_t a1, uint32_t a2,
                                         uint32_t a3, uint32_t b0, uint32_t b1) {
    asm volatile("mma.sync.aligned.m16n8k16.row.col.f32.bf16.bf16.f32 "
                 "{%0,%1,%2,%3}, {%4,%5,%6,%7}, {%8,%9}, {%0,%1,%2,%3};"
                 : "+f"(c[0]), "+f"(c[1]), "+f"(c[2]), "+f"(c[3])
                 : "r"(a0), "r"(a1), "r"(a2), "r"(a3), "r"(b0), "r"(b1));
}
__device__ __forceinline__ uint32_t pack_hi(float v0, float v1, float& rl0, float& rl1) {
    __nv_bfloat16 h0 = __float2bfloat16(v0);
    __nv_bfloat16 h1 = __float2bfloat16(v1);
    rl0 = v0 - __bfloat162float(h0);
    rl1 = v1 - __bfloat162float(h1);
    return ((uint32_t)__bfloat16_as_ushort(h1) << 16) | (uint32_t)__bfloat16_as_ushort(h0);
}
__device__ __forceinline__ uint32_t pack_lo(float l0, float l1) {
    return ((uint32_t)__bfloat16_as_ushort(__float2bfloat16(l1)) << 16) |
           (uint32_t)__bfloat16_as_ushort(__float2bfloat16(l0));
}

// ---------------- tensor-core GEMM via mma.sync: C = act(A(M,K)*W(N,K)^T + bias) -----
// Requires M % 128 == 0, N % 64 == 0. Split-bf16 (hi/lo, 3 terms) for ~fp32 accuracy.
#define LDA 40   // 32 cols + 8 pad (bf16), row = 80B
__global__ __launch_bounds__(256, 2)
void gemm_mma(const float* __restrict__ A, const float* __restrict__ W,
              const float* __restrict__ bias, float* __restrict__ C,
              int M, int K, int N, int doRelu) {
    __shared__ __nv_bfloat16 sAh[128][LDA];
    __shared__ __nv_bfloat16 sAl[128][LDA];
    __shared__ __nv_bfloat16 sWh[64][LDA];
    __shared__ __nv_bfloat16 sWl[64][LDA];

    const int tid = threadIdx.x;
    const int lane = tid & 31;
    const int wid = tid >> 5;
    const int warp_m = wid & 3;        // 0..3 -> 32-row slice
    const int warp_n = wid >> 2;       // 0..1 -> 32-col slice
    const int bm = blockIdx.x * 128, bn = blockIdx.y * 64;

    float acc[2][4][4];
#pragma unroll
    for (int t = 0; t < 2; t++)
#pragma unroll
        for (int u = 0; u < 4; u++)
#pragma unroll
            for (int i = 0; i < 4; i++) acc[t][u][i] = 0.0f;

    // ldmatrix source addresses (fixed per thread; add k-step col offset later)
    const uint32_t aAh = smem_u32(&sAh[0][0]);
    const uint32_t aAl = smem_u32(&sAl[0][0]);
    const uint32_t aWh = smem_u32(&sWh[0][0]);
    const uint32_t aWl = smem_u32(&sWl[0][0]);
    // A frag: row = warp_m*32 + t*16 + lane%16 ; col = ks*16 + (lane/16)*8
    const int a_r = warp_m * 32 + (lane & 15);
    const int a_c = (lane >> 4) << 3;
    // B frag: r=lane%8, mid=lane/8: row = warp_n*32 + pair*16 + (mid>>1)*8 + r ; col = ks*16 + (mid&1)*8
    const int b_r = warp_n * 32 + ((lane >> 4) << 3) + (lane & 7);
    const int b_c = ((lane >> 3) & 1) << 3;

    const int nch = (K + 31) >> 5;
    for (int ch = 0; ch < nch; ch++) {
        const int k0 = ch << 5;
        __syncthreads();
        // ---- fill A tiles: 128 rows x 32 cols (2048 bf16x2 stores) ----
#pragma unroll
        for (int i = 0; i < 8; i++) {
            int idx = (i << 8) + tid;
            int r = idx >> 4;
            int pc = (idx & 15) << 1;
            int gk = k0 + pc;
            const float* ap = A + (size_t)(bm + r) * K;
            float v0 = (gk < K) ? ap[gk] : 0.0f;
            float v1 = (gk + 1 < K) ? ap[gk + 1] : 0.0f;
            float l0, l1;
            uint32_t ph = pack_hi(v0, v1, l0, l1);
            *(uint32_t*)&sAh[r][pc] = ph;
            *(uint32_t*)&sAl[r][pc] = pack_lo(l0, l1);
        }
        // ---- fill W tiles: 64 rows x 32 cols ----
#pragma unroll
        for (int i = 0; i < 4; i++) {
            int idx = (i << 8) + tid;
            int r = idx >> 4;
            int pc = (idx & 15) << 1;
            int gk = k0 + pc;
            const float* wp = W + (size_t)(bn + r) * K;
            float v0 = (gk < K) ? wp[gk] : 0.0f;
            float v1 = (gk + 1 < K) ? wp[gk + 1] : 0.0f;
            float l0, l1;
            uint32_t ph = pack_hi(v0, v1, l0, l1);
            *(uint32_t*)&sWh[r][pc] = ph;
            *(uint32_t*)&sWl[r][pc] = pack_lo(l0, l1);
        }
        __syncthreads();

#pragma unroll
        for (int ks = 0; ks < 2; ks++) {
            const int kc = ks << 4;
            // A fragments (hi & lo) for 2 m-tiles
            uint32_t ah[2][4], al[2][4];
#pragma unroll
            for (int t = 0; t < 2; t++) {
                uint32_t off = (uint32_t)(((a_r + t * 16) * LDA + kc + a_c) * 2);
                ldm_x4(aAh + off, ah[t][0], ah[t][1], ah[t][2], ah[t][3]);
                ldm_x4(aAl + off, al[t][0], al[t][1], al[t][2], al[t][3]);
            }
            // B fragments (hi & lo) for 4 n-tiles (2 x4 loads each)
            uint32_t bh[4][2], bl[4][2];
#pragma unroll
            for (int p = 0; p < 2; p++) {
                uint32_t off = (uint32_t)(((b_r + p * 16) * LDA + kc + b_c) * 2);
                uint32_t q0, q1, q2, q3;
                ldm_x4(aWh + off, q0, q1, q2, q3);
                bh[p * 2][0] = q0; bh[p * 2][1] = q1;
                bh[p * 2 + 1][0] = q2; bh[p * 2 + 1][1] = q3;
                ldm_x4(aWl + off, q0, q1, q2, q3);
                bl[p * 2][0] = q0; bl[p * 2][1] = q1;
                bl[p * 2 + 1][0] = q2; bl[p * 2 + 1][1] = q3;
            }
            // 3-term split MMA
#pragma unroll
            for (int t = 0; t < 2; t++)
#pragma unroll
                for (int u = 0; u < 4; u++) {
                    mma_bf16(acc[t][u], ah[t][0], ah[t][1], ah[t][2], ah[t][3], bh[u][0], bh[u][1]);
                    mma_bf16(acc[t][u], ah[t][0], ah[t][1], ah[t][2], ah[t][3], bl[u][0], bl[u][1]);
                    mma_bf16(acc[t][u], al[t][0], al[t][1], al[t][2], al[t][3], bh[u][0], bh[u][1]);
                }
        }
    }

    // ---- epilogue: fused bias + relu, float2 stores ----
    const int g = lane >> 2;
    const int cpair = (lane & 3) << 1;
#pragma unroll
    for (int t = 0; t < 2; t++) {
#pragma unroll
        for (int u = 0; u < 4; u++) {
            int col = bn + warp_n * 32 + u * 8 + cpair;
            float b0 = bias[col], b1 = bias[col + 1];
            int r0 = bm + warp_m * 32 + t * 16 + g;
            float2 v0, v1;
            v0.x = acc[t][u][0] + b0; v0.y = acc[t][u][1] + b1;
            v1.x = acc[t][u][2] + b0; v1.y = acc[t][u][3] + b1;
            if (doRelu) {
                v0.x = fmaxf(v0.x, 0.0f); v0.y = fmaxf(v0.y, 0.0f);
                v1.x = fmaxf(v1.x, 0.0f); v1.y = fmaxf(v1.y, 0.0f);
            }
            *(float2*)(C + (size_t)r0 * N + col) = v0;
            *(float2*)(C + (size_t)(r0 + 8) * N + col) = v1;
        }
    }
}

// ---------------- FPS: one block per batch, points in registers ----------------
template <int PPT>
__global__ void fps_kernel(const float* __restrict__ pts, int N, int S,
                           long strideB, int sp, int sc,
                           int* __restrict__ outIdx, float* __restrict__ outXyz) {
    const int T = 512;
    int b = blockIdx.x;
    int t = threadIdx.x;
    const float* base = pts + (size_t)b * strideB;

    float px[PPT], py[PPT], pz[PPT], dist[PPT];
#pragma unroll
    for (int j = 0; j < PPT; j++) {
        int i = t + j * T;
        px[j] = base[(size_t)i * sp];
        py[j] = base[(size_t)i * sp + sc];
        pz[j] = base[(size_t)i * sp + 2 * (size_t)sc];
        dist[j] = 1e10f;
    }

    __shared__ float s_c[3];
    __shared__ float s_v[16];
    __shared__ int   s_i[16];
    __shared__ int   s_far;

    if (t == 0) {
        s_far = 0;
        outIdx[(size_t)b * S] = 0;
        s_c[0] = px[0]; s_c[1] = py[0]; s_c[2] = pz[0];
        float* ox = outXyz + ((size_t)b * S) * 3;
        ox[0] = px[0]; ox[1] = py[0]; ox[2] = pz[0];
    }
    __syncthreads();

    for (int it = 0; it < S - 1; it++) {
        float cx = s_c[0], cy = s_c[1], cz = s_c[2];
        float bestv = -1.0f;
        int   besti = 0x7fffffff;
#pragma unroll
        for (int j = 0; j < PPT; j++) {
            float d = sqd(px[j] - cx, py[j] - cy, pz[j] - cz);
            float nd = fminf(dist[j], d);
            dist[j] = nd;
            if (nd > bestv) { bestv = nd; besti = t + j * T; }
        }
#pragma unroll
        for (int off = 16; off; off >>= 1) {
            float ov = __shfl_down_sync(0xffffffffu, bestv, off);
            int   oi = __shfl_down_sync(0xffffffffu, besti, off);
            if (ov > bestv || (ov == bestv && oi < besti)) { bestv = ov; besti = oi; }
        }
        if ((t & 31) == 0) { s_v[t >> 5] = bestv; s_i[t >> 5] = besti; }
        __syncthreads();
        if (t < 32) {
            float v = (t < 16) ? s_v[t] : -1.0f;
            int   ii = (t < 16) ? s_i[t] : 0x7fffffff;
#pragma unroll
            for (int off = 16; off; off >>= 1) {
                float ov = __shfl_down_sync(0xffffffffu, v, off);
                int   oi = __shfl_down_sync(0xffffffffu, ii, off);
                if (ov > v || (ov == v && oi < ii)) { v = ov; ii = oi; }
            }
            if (t == 0) s_far = ii;
        }
        __syncthreads();
        int far = s_far;
        if (t == (far & (T - 1))) {
            int j = far >> 9;
            s_c[0] = px[j]; s_c[1] = py[j]; s_c[2] = pz[j];
            outIdx[(size_t)b * S + it + 1] = far;
            float* ox = outXyz + ((size_t)b * S + it + 1) * 3;
            ox[0] = px[j]; ox[1] = py[j]; ox[2] = pz[j];
        }
        __syncthreads();
    }
}

// ---------------- ball query + grouping, SA1 ----------------
__global__ void bq_group1(const float* __restrict__ xyz,
                          const float* __restrict__ cent,
                          float* __restrict__ out) {
    extern __shared__ float sm[];
    float* sx = sm; float* sy = sm + N1; float* sz = sm + 2 * N1;
    __shared__ int sel[8][G1];
    int b = blockIdx.x;
    const float* base = xyz + (size_t)b * 3 * N1;
    for (int i = threadIdx.x; i < N1; i += blockDim.x) {
        sx[i] = base[i]; sy[i] = base[N1 + i]; sz[i] = base[2 * N1 + i];
    }
    __syncthreads();
    const float R2 = (float)(0.2 * 0.2);
    int warp = threadIdx.x >> 5, lane = threadIdx.x & 31;
    for (int s = blockIdx.y * 8 + warp; s < S1; s += gridDim.y * 8) {
        const float* cc = cent + ((size_t)b * S1 + s) * 3;
        float cx = cc[0], cy = cc[1], cz = cc[2];
        int cnt = 0, first = -1;
        for (int bi = 0; bi < N1; bi += 32) {
            int i = bi + lane;
            float d = sqd(sx[i] - cx, sy[i] - cy, sz[i] - cz);
            bool ok = (d <= R2);
            unsigned m = __ballot_sync(0xffffffffu, ok);
            if (m) {
                if (first < 0) first = bi + __ffs(m) - 1;
                int pos = cnt + __popc(m & ((1u << lane) - 1u));
                if (ok && pos < G1) sel[warp][pos] = i;
                cnt += __popc(m);
                if (cnt >= G1) break;
            }
        }
        for (int p = cnt + lane; p < G1; p += 32) sel[warp][p] = first;
        __syncwarp();
        int i = sel[warp][lane];
        size_t row = (((size_t)(b * S1 + s)) * G1 + lane) * 3;
        out[row + 0] = sx[i] - cx;
        out[row + 1] = sy[i] - cy;
        out[row + 2] = sz[i] - cz;
        __syncwarp();
    }
}

// ---------------- ball query + grouping, SA2 ----------------
__global__ void bq_group2(const float* __restrict__ pts,
                          const float* __restrict__ cent,
                          const float* __restrict__ feat,
                          float* __restrict__ out) {
    __shared__ float sx[512], sy[512], sz[512];
    __shared__ int sel[8][G2];
    int b = blockIdx.x;
    const float* base = pts + (size_t)b * 512 * 3;
    for (int i = threadIdx.x; i < 512; i += blockDim.x) {
        sx[i] = base[i * 3]; sy[i] = base[i * 3 + 1]; sz[i] = base[i * 3 + 2];
    }
    __syncthreads();
    const float R2 = (float)(0.4 * 0.4);
    int warp = threadIdx.x >> 5, lane = threadIdx.x & 31;
    for (int s = blockIdx.y * 8 + warp; s < S2; s += gridDim.y * 8) {
        const float* cc = cent + ((size_t)b * S2 + s) * 3;
        float cx = cc[0], cy = cc[1], cz = cc[2];
        int cnt = 0, first = -1;
        for (int bi = 0; bi < 512; bi += 32) {
            int i = bi + lane;
            float d = sqd(sx[i] - cx, sy[i] - cy, sz[i] - cz);
            bool ok = (d <= R2);
            unsigned m = __ballot_sync(0xffffffffu, ok);
            if (m) {
                if (first < 0) first = bi + __ffs(m) - 1;
                int pos = cnt + __popc(m & ((1u << lane) - 1u));
                if (ok && pos < G2) sel[warp][pos] = i;
                cnt += __popc(m);
                if (cnt >= G2) break;
            }
        }
        for (int p = cnt + lane; p < G2; p += 32) sel[warp][p] = first;
        __syncwarp();
        for (int n = 0; n < G2; n++) {
            int i = sel[warp][n];
            float* row = out + ((((size_t)(b * S2 + s)) * G2) + n) * 131;
            if (lane == 0) {
                row[0] = sx[i] - cx; row[1] = sy[i] - cy; row[2] = sz[i] - cz;
            }
            const float* f = feat + ((size_t)(b * 512) + i) * 128;
            for (int c = lane; c < 128; c += 32) row[3 + c] = f[c];
        }
        __syncwarp();
    }
}

// ---------------- dedicated K=3 layer (memory bound, exact fp32) ----------------
__global__ void mlp_k3(const float* __restrict__ A, const float* __restrict__ W,
                       const float* __restrict__ bias, float* __restrict__ C, int M) {
    __shared__ float w[192], bb[64];
    if (threadIdx.x < 192) w[threadIdx.x] = W[threadIdx.x];
    if (threadIdx.x < 64) bb[threadIdx.x] = bias[threadIdx.x];
    __syncthreads();
    int gid = blockIdx.x * blockDim.x + threadIdx.x;
    int m = gid >> 6, o = gid & 63;
    if (m >= M) return;
    float a0 = A[(size_t)m * 3 + 0], a1 = A[(size_t)m * 3 + 1], a2 = A[(size_t)m * 3 + 2];
    float v = bb[o] + a0 * w[o * 3 + 0] + a1 * w[o * 3 + 1] + a2 * w[o * 3 + 2];
    C[(size_t)gid] = fmaxf(v, 0.0f);
}

// ---------------- generic fp32 GEMM (small head layers, M=32) ----------------
#define BM 128
#define BN 64
#define BK 16
__global__ void gemm_bias_act(const float* __restrict__ A, const float* __restrict__ W,
                              const float* __restrict__ bias, float* __restrict__ C,
                              int M, int K, int N, int doRelu) {
    __shared__ float As[BK][BM + 4];
    __shared__ float Ws[BK][BN];
    int bm = blockIdx.x * BM, bn = blockIdx.y * BN;
    int tid = threadIdx.x;
    int tx = tid & 15, ty = tid >> 4;
    float acc[8][4] = {};

    for (int k0 = 0; k0 < K; k0 += BK) {
        int lr = tid >> 1, lk0 = (tid & 1) * 8;
        int gm = bm + lr;
#pragma unroll
        for (int i = 0; i < 8; i++) {
            int kk = k0 + lk0 + i;
            As[lk0 + i][lr] = (gm < M && kk < K) ? A[(size_t)gm * K + kk] : 0.0f;
        }
        int ln = tid >> 2, lkw = (tid & 3) * 4;
        int gn = bn + ln;
#pragma unroll
        for (int i = 0; i < 4; i++) {
            int kk = k0 + lkw + i;
            Ws[lkw + i][ln] = (gn < N && kk < K) ? W[(size_t)gn * K + kk] : 0.0f;
        }
        __syncthreads();
#pragma unroll
        for (int k = 0; k < BK; k++) {
            float a[8], bvv[4];
#pragma unroll
            for (int i = 0; i < 8; i++) a[i] = As[k][ty * 8 + i];
#pragma unroll
            for (int j = 0; j < 4; j++) bvv[j] = Ws[k][tx * 4 + j];
#pragma unroll
            for (int i = 0; i < 8; i++)
#pragma unroll
                for (int j = 0; j < 4; j++) acc[i][j] += a[i] * bvv[j];
        }
        __syncthreads();
    }
#pragma unroll
    for (int j = 0; j < 4; j++) {
        int gn = bn + tx * 4 + j;
        if (gn >= N) continue;
        float bv = bias[gn];
#pragma unroll
        for (int i = 0; i < 8; i++) {
            int gm = bm + ty * 8 + i;
            if (gm < M) {
                float v = acc[i][j] + bv;
                if (doRelu) v = fmaxf(v, 0.0f);
                C[(size_t)gm * N + gn] = v;
            }
        }
    }
}

// ---------------- max pool over group dim ----------------
__global__ void maxpool_kernel(const float* __restrict__ in, float* __restrict__ out,
                               int S, int G, int C) {
    int idx = blockIdx.x * blockDim.x + threadIdx.x;
    if (idx >= S * C) return;
    int s = idx / C, c = idx - s * C;
    const float* p = in + ((size_t)s * G) * C + c;
    float v = p[0];
    for (int g = 1; g < G; g++) v = fmaxf(v, p[(size_t)g * C]);
    out[idx] = v;
}

// ---------------- SA3 concat ----------------
__global__ void concat_sa3(const float* __restrict__ cent2, const float* __restrict__ l2p,
                           float* __restrict__ out) {
    int idx = blockIdx.x * blockDim.x + threadIdx.x;
    const int TOT = BATCH * S2 * 259;
    if (idx >= TOT) return;
    int r = idx / 259, c = idx - r * 259;
    out[idx] = (c < 3) ? cent2[r * 3 + c] : l2p[(size_t)r * 256 + (c - 3)];
}

// ---------------- orchestration ----------------
static inline void launch_gemm_simt(const float* A, const float* W, const float* bias, float* C,
                                    int M, int K, int N, int relu) {
    dim3 grid((M + BM - 1) / BM, (N + BN - 1) / BN);
    gemm_bias_act<<<grid, 256>>>(A, W, bias, C, M, K, N, relu);
}
static inline void launch_gemm_tc(const float* A, const float* W, const float* bias, float* C,
                                  int M, int K, int N, int relu) {
    dim3 grid(M / 128, N / 64);
    gemm_mma<<<grid, 256>>>(A, W, bias, C, M, K, N, relu);
}

extern "C" void kernel_launch(void* const* d_in, const int* in_sizes, int n_in,
                              void* d_out, int out_size) {
    (void)in_sizes; (void)n_in; (void)out_size;
    const float* xyz  = (const float*)d_in[0];
    const float* s1w0 = (const float*)d_in[1];  const float* s1b0 = (const float*)d_in[2];
    const float* s1w1 = (const float*)d_in[3];  const float* s1b1 = (const float*)d_in[4];
    const float* s1w2 = (const float*)d_in[5];  const float* s1b2 = (const float*)d_in[6];
    const float* s2w0 = (const float*)d_in[7];  const float* s2b0 = (const float*)d_in[8];
    const float* s2w1 = (const float*)d_in[9];  const float* s2b1 = (const float*)d_in[10];
    const float* s2w2 = (const float*)d_in[11]; const float* s2b2 = (const float*)d_in[12];
    const float* s3w0 = (const float*)d_in[13]; const float* s3b0 = (const float*)d_in[14];
    const float* s3w1 = (const float*)d_in[15]; const float* s3b1 = (const float*)d_in[16];
    const float* s3w2 = (const float*)d_in[17]; const float* s3b2 = (const float*)d_in[18];
    const float* f1w  = (const float*)d_in[19]; const float* f1b  = (const float*)d_in[20];
    const float* f2w  = (const float*)d_in[21]; const float* f2b  = (const float*)d_in[22];
    const float* f3w  = (const float*)d_in[23]; const float* f3b  = (const float*)d_in[24];
    float* out = (float*)d_out;

    float *bufA, *bufB, *cent1, *cent2, *l1p, *l2p, *featv;
    int *idx1, *idx2;
    cudaGetSymbolAddress((void**)&bufA, g_bufA);
    cudaGetSymbolAddress((void**)&bufB, g_bufB);
    cudaGetSymbolAddress((void**)&cent1, g_cent1);
    cudaGetSymbolAddress((void**)&cent2, g_cent2);
    cudaGetSymbolAddress((void**)&l1p, g_l1p);
    cudaGetSymbolAddress((void**)&l2p, g_l2p);
    cudaGetSymbolAddress((void**)&featv, g_feat);
    cudaGetSymbolAddress((void**)&idx1, g_idx1);
    cudaGetSymbolAddress((void**)&idx2, g_idx2);

    cudaFuncSetAttribute(bq_group1, cudaFuncAttributeMaxDynamicSharedMemorySize, 3 * N1 * 4);

    const int M1 = BATCH * S1 * G1;   // 524288
    const int M2 = BATCH * S2 * G2;   // 262144
    const int M3 = BATCH * S2;        // 4096

    // ---- SA1 ----
    fps_kernel<8><<<BATCH, 512>>>(xyz, N1, S1, (long)3 * N1, 1, N1, idx1, cent1);
    bq_group1<<<dim3(BATCH, 8), 256, 3 * N1 * 4>>>(xyz, cent1, bufA);
    mlp_k3<<<(M1 * 64) / 256, 256>>>(bufA, s1w0, s1b0, bufB, M1);
    launch_gemm_tc(bufB, s1w1, s1b1, bufA, M1, 64, 64, 1);
    launch_gemm_tc(bufA, s1w2, s1b2, bufB, M1, 64, 128, 1);
    maxpool_kernel<<<(BATCH * S1 * 128 + 255) / 256, 256>>>(bufB, l1p, BATCH * S1, G1, 128);

    // ---- SA2 ----
    fps_kernel<1><<<BATCH, 512>>>(cent1, S1, S2, (long)S1 * 3, 3, 1, idx2, cent2);
    bq_group2<<<dim3(BATCH, 2), 256>>>(cent1, cent2, l1p, bufA);
    launch_gemm_tc(bufA, s2w0, s2b0, bufB, M2, 131, 128, 1);
    launch_gemm_tc(bufB, s2w1, s2b1, bufA, M2, 128, 128, 1);
    launch_gemm_tc(bufA, s2w2, s2b2, bufB, M2, 128, 256, 1);
    maxpool_kernel<<<(BATCH * S2 * 256 + 255) / 256, 256>>>(bufB, l2p, BATCH * S2, G2, 256);

    // ---- SA3 (group all) ----
    concat_sa3<<<(M3 * 259 + 255) / 256, 256>>>(cent2, l2p, bufA);
    launch_gemm_tc(bufA, s3w0, s3b0, bufB, M3, 259, 256, 1);
    launch_gemm_tc(bufB, s3w1, s3b1, bufA, M3, 256, 512, 1);
    launch_gemm_tc(bufA, s3w2, s3b2, bufB, M3, 512, 1024, 1);
    maxpool_kernel<<<(BATCH * 1024 + 255) / 256, 256>>>(bufB, featv, BATCH, S2, 1024);

    // ---- head (tiny) ----
    launch_gemm_simt(featv, f1w, f1b, bufA, BATCH, 1024, 512, 1);
    launch_gemm_simt(bufA, f2w, f2b, bufB, BATCH, 512, 256, 1);
    launch_gemm_simt(bufB, f3w, f3b, out, BATCH, 256, 6, 0);
}

// round 4
// speedup vs baseline: 1.8542x; 1.1448x over previous
#include <cuda_runtime.h>
#include <cuda_bf16.h>
#include <cstdint>

// ---------------- problem constants ----------------
#define BATCH 32
#define N1 4096
#define S1 512
#define G1 32
#define S2 128
#define G2 64

// ---------------- scratch (device globals; no cudaMalloc allowed) ----------------
__device__ float g_bufA[36u * 1024u * 1024u];
__device__ float g_bufB[68u * 1024u * 1024u];
__device__ float g_cent1[BATCH * S1 * 3];
__device__ float g_cent2[BATCH * S2 * 3];
__device__ int   g_idx1[BATCH * S1];
__device__ int   g_idx2[BATCH * S2];
__device__ float g_l1p[BATCH * S1 * 128];
__device__ float g_l2p[BATCH * S2 * 256];
__device__ float g_feat[BATCH * 1024];

// squared distance with NO fma contraction, same assoc order as jnp.sum over last axis
__device__ __forceinline__ float sqd(float dx, float dy, float dz) {
    return __fadd_rn(__fadd_rn(__fmul_rn(dx, dx), __fmul_rn(dy, dy)), __fmul_rn(dz, dz));
}

// ================= mma.sync helpers (base PTX, works on compute_103) =================
__device__ __forceinline__ uint32_t smem_u32(const void* p) {
    uint32_t a;
    asm("{ .reg .u64 t; cvta.to.shared.u64 t, %1; cvt.u32.u64 %0, t; }" : "=r"(a) : "l"(p));
    return a;
}
__device__ __forceinline__ void ldm_x4(uint32_t addr, uint32_t& r0, uint32_t& r1,
                                       uint32_t& r2, uint32_t& r3) {
    asm volatile("ldmatrix.sync.aligned.m8n8.x4.shared.b16 {%0,%1,%2,%3}, [%4];"
                 : "=r"(r0), "=r"(r1), "=r"(r2), "=r"(r3) : "r"(addr));
}
__device__ __forceinline__ void mma_bf16(float* c, uint32_t a0, uint32_t a1, uint32_t a2,
                                         uint32_t a3, uint32_t b0, uint32_t b1) {
    asm volatile("mma.sync.aligned.m16n8k16.row.col.f32.bf16.bf16.f32 "
                 "{%0,%1,%2,%3}, {%4,%5,%6,%7}, {%8,%9}, {%0,%1,%2,%3};"
                 : "+f"(c[0]), "+f"(c[1]), "+f"(c[2]), "+f"(c[3])
                 : "r"(a0), "r"(a1), "r"(a2), "r"(a3), "r"(b0), "r"(b1));
}
__device__ __forceinline__ uint32_t pack_hi(float v0, float v1, float& rl0, float& rl1) {
    __nv_bfloat16 h0 = __float2bfloat16(v0);
    __nv_bfloat16 h1 = __float2bfloat16(v1);
    rl0 = v0 - __bfloat162float(h0);
    rl1 = v1 - __bfloat162float(h1);
    return ((uint32_t)__bfloat16_as_ushort(h1) << 16) | (uint32_t)__bfloat16_as_ushort(h0);
}
__device__ __forceinline__ uint32_t pack_lo(float l0, float l1) {
    return ((uint32_t)__bfloat16_as_ushort(__float2bfloat16(l1)) << 16) |
           (uint32_t)__bfloat16_as_ushort(__float2bfloat16(l0));
}

// ---------------- tensor-core GEMM via mma.sync: C = act(A(M,K)*W(N,K)^T + bias) -----
// Requires M % 128 == 0, N % 64 == 0. Split-bf16 (hi/lo, 3 terms) for ~fp32 accuracy.
// GEN0:  A is generated on the fly as relu(W0(64,3) @ xyz(M,3)^T + B0)  (K must be 64)
// POOLG: 0 = plain output; 32/64/128 = fused max-pool over groups of POOLG rows,
//        output row s = bm/POOLG + g, width N. (always applies ReLU)
#define LDA 40   // 32 cols + 8 pad (bf16), row = 80B
template <int GEN0, int POOLG>
__global__ __launch_bounds__(256, 2)
void gemm_mma(const float* __restrict__ A, const float* __restrict__ W,
              const float* __restrict__ bias, float* __restrict__ C,
              int M, int K, int N, int doRelu,
              const float* __restrict__ W0, const float* __restrict__ B0,
              const float* __restrict__ GXYZ) {
    __shared__ __nv_bfloat16 sAh[128][LDA];
    __shared__ __nv_bfloat16 sAl[128][LDA];
    __shared__ __nv_bfloat16 sWh[64][LDA];
    __shared__ __nv_bfloat16 sWl[64][LDA];
    __shared__ float pool[4][64];
    __shared__ float sxyz[128][4];
    __shared__ float sW0[192];
    __shared__ float sB0v[64];

    const int tid = threadIdx.x;
    const int lane = tid & 31;
    const int wid = tid >> 5;
    const int warp_m = wid & 3;        // 0..3 -> 32-row slice
    const int warp_n = wid >> 2;       // 0..1 -> 32-col slice
    const int bm = blockIdx.x * 128, bn = blockIdx.y * 64;

    if (GEN0) {
        if (tid < 192) sW0[tid] = W0[tid];
        if (tid < 64) sB0v[tid] = B0[tid];
        if (tid < 128) {
            const float* g = GXYZ + (size_t)(bm + tid) * 3;
            sxyz[tid][0] = g[0]; sxyz[tid][1] = g[1]; sxyz[tid][2] = g[2];
        }
    }

    float acc[2][4][4];
#pragma unroll
    for (int t = 0; t < 2; t++)
#pragma unroll
        for (int u = 0; u < 4; u++)
#pragma unroll
            for (int i = 0; i < 4; i++) acc[t][u][i] = 0.0f;

    const uint32_t aAh = smem_u32(&sAh[0][0]);
    const uint32_t aAl = smem_u32(&sAl[0][0]);
    const uint32_t aWh = smem_u32(&sWh[0][0]);
    const uint32_t aWl = smem_u32(&sWl[0][0]);
    const int a_r = warp_m * 32 + (lane & 15);
    const int a_c = (lane >> 4) << 3;
    const int b_r = warp_n * 32 + ((lane >> 4) << 3) + (lane & 7);
    const int b_c = ((lane >> 3) & 1) << 3;

    const int nch = (K + 31) >> 5;
    for (int ch = 0; ch < nch; ch++) {
        const int k0 = ch << 5;
        __syncthreads();
        // ---- fill A tiles: 128 rows x 32 cols ----
#pragma unroll
        for (int i = 0; i < 8; i++) {
            int idx = (i << 8) + tid;
            int r = idx >> 4;
            int pc = (idx & 15) << 1;
            int gk = k0 + pc;
            float v0, v1;
            if (GEN0) {
                // layer0: relu(b0[k] + dot(xyz[r], W0[k]))   (K == 64, always in range)
                float x = sxyz[r][0], y = sxyz[r][1], z = sxyz[r][2];
                v0 = fmaxf(sB0v[gk] + x * sW0[gk * 3] + y * sW0[gk * 3 + 1] + z * sW0[gk * 3 + 2], 0.0f);
                v1 = fmaxf(sB0v[gk + 1] + x * sW0[gk * 3 + 3] + y * sW0[gk * 3 + 4] + z * sW0[gk * 3 + 5], 0.0f);
            } else {
                const float* ap = A + (size_t)(bm + r) * K;
                v0 = (gk < K) ? ap[gk] : 0.0f;
                v1 = (gk + 1 < K) ? ap[gk + 1] : 0.0f;
            }
            float l0, l1;
            uint32_t ph = pack_hi(v0, v1, l0, l1);
            *(uint32_t*)&sAh[r][pc] = ph;
            *(uint32_t*)&sAl[r][pc] = pack_lo(l0, l1);
        }
        // ---- fill W tiles: 64 rows x 32 cols ----
#pragma unroll
        for (int i = 0; i < 4; i++) {
            int idx = (i << 8) + tid;
            int r = idx >> 4;
            int pc = (idx & 15) << 1;
            int gk = k0 + pc;
            const float* wp = W + (size_t)(bn + r) * K;
            float v0 = (gk < K) ? wp[gk] : 0.0f;
            float v1 = (gk + 1 < K) ? wp[gk + 1] : 0.0f;
            float l0, l1;
            uint32_t ph = pack_hi(v0, v1, l0, l1);
            *(uint32_t*)&sWh[r][pc] = ph;
            *(uint32_t*)&sWl[r][pc] = pack_lo(l0, l1);
        }
        __syncthreads();

#pragma unroll
        for (int ks = 0; ks < 2; ks++) {
            const int kc = ks << 4;
            uint32_t ah[2][4], al[2][4];
#pragma unroll
            for (int t = 0; t < 2; t++) {
                uint32_t off = (uint32_t)(((a_r + t * 16) * LDA + kc + a_c) * 2);
                ldm_x4(aAh + off, ah[t][0], ah[t][1], ah[t][2], ah[t][3]);
                ldm_x4(aAl + off, al[t][0], al[t][1], al[t][2], al[t][3]);
            }
            uint32_t bh[4][2], bl[4][2];
#pragma unroll
            for (int p = 0; p < 2; p++) {
                uint32_t off = (uint32_t)(((b_r + p * 16) * LDA + kc + b_c) * 2);
                uint32_t q0, q1, q2, q3;
                ldm_x4(aWh + off, q0, q1, q2, q3);
                bh[p * 2][0] = q0; bh[p * 2][1] = q1;
                bh[p * 2 + 1][0] = q2; bh[p * 2 + 1][1] = q3;
                ldm_x4(aWl + off, q0, q1, q2, q3);
                bl[p * 2][0] = q0; bl[p * 2][1] = q1;
                bl[p * 2 + 1][0] = q2; bl[p * 2 + 1][1] = q3;
            }
#pragma unroll
            for (int t = 0; t < 2; t++)
#pragma unroll
                for (int u = 0; u < 4; u++) {
                    mma_bf16(acc[t][u], ah[t][0], ah[t][1], ah[t][2], ah[t][3], bh[u][0], bh[u][1]);
                    mma_bf16(acc[t][u], ah[t][0], ah[t][1], ah[t][2], ah[t][3], bl[u][0], bl[u][1]);
                    mma_bf16(acc[t][u], al[t][0], al[t][1], al[t][2], al[t][3], bh[u][0], bh[u][1]);
                }
        }
    }

    const int g = lane >> 2;
    const int cpair = (lane & 3) << 1;

    if (POOLG == 0) {
        // ---- plain epilogue: fused bias + relu, float2 stores ----
#pragma unroll
        for (int t = 0; t < 2; t++) {
#pragma unroll
            for (int u = 0; u < 4; u++) {
                int col = bn + warp_n * 32 + u * 8 + cpair;
                float b0 = bias[col], b1 = bias[col + 1];
                int r0 = bm + warp_m * 32 + t * 16 + g;
                float2 v0, v1;
                v0.x = acc[t][u][0] + b0; v0.y = acc[t][u][1] + b1;
                v1.x = acc[t][u][2] + b0; v1.y = acc[t][u][3] + b1;
                if (doRelu) {
                    v0.x = fmaxf(v0.x, 0.0f); v0.y = fmaxf(v0.y, 0.0f);
                    v1.x = fmaxf(v1.x, 0.0f); v1.y = fmaxf(v1.y, 0.0f);
                }
                *(float2*)(C + (size_t)r0 * N + col) = v0;
                *(float2*)(C + (size_t)(r0 + 8) * N + col) = v1;
            }
        }
    } else {
        // ---- fused max-pool epilogue (always relu) ----
#pragma unroll
        for (int u = 0; u < 4; u++) {
            int col = bn + warp_n * 32 + u * 8 + cpair;
            float b0 = bias[col], b1 = bias[col + 1];
            // max over this thread's 4 rows
            float m0 = fmaxf(fmaxf(acc[0][u][0], acc[0][u][2]), fmaxf(acc[1][u][0], acc[1][u][2]));
            float m1 = fmaxf(fmaxf(acc[0][u][1], acc[0][u][3]), fmaxf(acc[1][u][1], acc[1][u][3]));
            // reduce across the 8 lanes sharing these columns (bits 2..4 of lane)
#pragma unroll
            for (int off = 4; off < 32; off <<= 1) {
                m0 = fmaxf(m0, __shfl_xor_sync(0xffffffffu, m0, off));
                m1 = fmaxf(m1, __shfl_xor_sync(0xffffffffu, m1, off));
            }
            m0 = fmaxf(m0 + b0, 0.0f);
            m1 = fmaxf(m1 + b1, 0.0f);
            if (POOLG == 32) {
                if (lane < 4) {
                    int s = bm / 32 + warp_m;
                    C[(size_t)s * N + col] = m0;
                    C[(size_t)s * N + col + 1] = m1;
                }
            } else {
                if (lane < 4) {
                    int lc = warp_n * 32 + u * 8 + cpair;
                    pool[warp_m][lc] = m0;
                    pool[warp_m][lc + 1] = m1;
                }
            }
        }
        if (POOLG > 32) {
            __syncthreads();
            if (POOLG == 64) {
                if (tid < 128) {
                    int gg = tid >> 6, c = tid & 63;
                    float v = fmaxf(pool[2 * gg][c], pool[2 * gg + 1][c]);
                    C[(size_t)(bm / 64 + gg) * N + bn + c] = v;
                }
            } else {  // 128
                if (tid < 64) {
                    float v = fmaxf(fmaxf(pool[0][tid], pool[1][tid]),
                                    fmaxf(pool[2][tid], pool[3][tid]));
                    C[(size_t)(bm / 128) * N + bn + tid] = v;
                }
            }
        }
    }
}

// ---------------- FPS: one block per batch, points in registers ----------------
template <int PPT>
__global__ void fps_kernel(const float* __restrict__ pts, int N, int S,
                           long strideB, int sp, int sc,
                           int* __restrict__ outIdx, float* __restrict__ outXyz) {
    const int T = 512;
    int b = blockIdx.x;
    int t = threadIdx.x;
    const float* base = pts + (size_t)b * strideB;

    float px[PPT], py[PPT], pz[PPT], dist[PPT];
#pragma unroll
    for (int j = 0; j < PPT; j++) {
        int i = t + j * T;
        px[j] = base[(size_t)i * sp];
        py[j] = base[(size_t)i * sp + sc];
        pz[j] = base[(size_t)i * sp + 2 * (size_t)sc];
        dist[j] = 1e10f;
    }

    __shared__ float s_c[3];
    __shared__ float s_v[16];
    __shared__ int   s_i[16];
    __shared__ int   s_far;

    if (t == 0) {
        s_far = 0;
        outIdx[(size_t)b * S] = 0;
        s_c[0] = px[0]; s_c[1] = py[0]; s_c[2] = pz[0];
        float* ox = outXyz + ((size_t)b * S) * 3;
        ox[0] = px[0]; ox[1] = py[0]; ox[2] = pz[0];
    }
    __syncthreads();

    for (int it = 0; it < S - 1; it++) {
        float cx = s_c[0], cy = s_c[1], cz = s_c[2];
        float bestv = -1.0f;
        int   besti = 0x7fffffff;
#pragma unroll
        for (int j = 0; j < PPT; j++) {
            float d = sqd(px[j] - cx, py[j] - cy, pz[j] - cz);
            float nd = fminf(dist[j], d);
            dist[j] = nd;
            if (nd > bestv) { bestv = nd; besti = t + j * T; }
        }
#pragma unroll
        for (int off = 16; off; off >>= 1) {
            float ov = __shfl_down_sync(0xffffffffu, bestv, off);
            int   oi = __shfl_down_sync(0xffffffffu, besti, off);
            if (ov > bestv || (ov == bestv && oi < besti)) { bestv = ov; besti = oi; }
        }
        if ((t & 31) == 0) { s_v[t >> 5] = bestv; s_i[t >> 5] = besti; }
        __syncthreads();
        if (t < 32) {
            float v = (t < 16) ? s_v[t] : -1.0f;
            int   ii = (t < 16) ? s_i[t] : 0x7fffffff;
#pragma unroll
            for (int off = 16; off; off >>= 1) {
                float ov = __shfl_down_sync(0xffffffffu, v, off);
                int   oi = __shfl_down_sync(0xffffffffu, ii, off);
                if (ov > v || (ov == v && oi < ii)) { v = ov; ii = oi; }
            }
            if (t == 0) s_far = ii;
        }
        __syncthreads();
        int far = s_far;
        if (t == (far & (T - 1))) {
            int j = far >> 9;
            s_c[0] = px[j]; s_c[1] = py[j]; s_c[2] = pz[j];
            outIdx[(size_t)b * S + it + 1] = far;
            float* ox = outXyz + ((size_t)b * S + it + 1) * 3;
            ox[0] = px[j]; ox[1] = py[j]; ox[2] = pz[j];
        }
        __syncthreads();
    }
}

// ---------------- ball query + grouping, SA1 ----------------
__global__ void bq_group1(const float* __restrict__ xyz,
                          const float* __restrict__ cent,
                          float* __restrict__ out) {
    extern __shared__ float sm[];
    float* sx = sm; float* sy = sm + N1; float* sz = sm + 2 * N1;
    __shared__ int sel[8][G1];
    int b = blockIdx.x;
    const float* base = xyz + (size_t)b * 3 * N1;
    for (int i = threadIdx.x; i < N1; i += blockDim.x) {
        sx[i] = base[i]; sy[i] = base[N1 + i]; sz[i] = base[2 * N1 + i];
    }
    __syncthreads();
    const float R2 = (float)(0.2 * 0.2);
    int warp = threadIdx.x >> 5, lane = threadIdx.x & 31;
    for (int s = blockIdx.y * 8 + warp; s < S1; s += gridDim.y * 8) {
        const float* cc = cent + ((size_t)b * S1 + s) * 3;
        float cx = cc[0], cy = cc[1], cz = cc[2];
        int cnt = 0, first = -1;
        for (int bi = 0; bi < N1; bi += 32) {
            int i = bi + lane;
            float d = sqd(sx[i] - cx, sy[i] - cy, sz[i] - cz);
            bool ok = (d <= R2);
            unsigned m = __ballot_sync(0xffffffffu, ok);
            if (m) {
                if (first < 0) first = bi + __ffs(m) - 1;
                int pos = cnt + __popc(m & ((1u << lane) - 1u));
                if (ok && pos < G1) sel[warp][pos] = i;
                cnt += __popc(m);
                if (cnt >= G1) break;
            }
        }
        for (int p = cnt + lane; p < G1; p += 32) sel[warp][p] = first;
        __syncwarp();
        int i = sel[warp][lane];
        size_t row = (((size_t)(b * S1 + s)) * G1 + lane) * 3;
        out[row + 0] = sx[i] - cx;
        out[row + 1] = sy[i] - cy;
        out[row + 2] = sz[i] - cz;
        __syncwarp();
    }
}

// ---------------- ball query + grouping, SA2 ----------------
__global__ void bq_group2(const float* __restrict__ pts,
                          const float* __restrict__ cent,
                          const float* __restrict__ feat,
                          float* __restrict__ out) {
    __shared__ float sx[512], sy[512], sz[512];
    __shared__ int sel[8][G2];
    int b = blockIdx.x;
    const float* base = pts + (size_t)b * 512 * 3;
    for (int i = threadIdx.x; i < 512; i += blockDim.x) {
        sx[i] = base[i * 3]; sy[i] = base[i * 3 + 1]; sz[i] = base[i * 3 + 2];
    }
    __syncthreads();
    const float R2 = (float)(0.4 * 0.4);
    int warp = threadIdx.x >> 5, lane = threadIdx.x & 31;
    for (int s = blockIdx.y * 8 + warp; s < S2; s += gridDim.y * 8) {
        const float* cc = cent + ((size_t)b * S2 + s) * 3;
        float cx = cc[0], cy = cc[1], cz = cc[2];
        int cnt = 0, first = -1;
        for (int bi = 0; bi < 512; bi += 32) {
            int i = bi + lane;
            float d = sqd(sx[i] - cx, sy[i] - cy, sz[i] - cz);
            bool ok = (d <= R2);
            unsigned m = __ballot_sync(0xffffffffu, ok);
            if (m) {
                if (first < 0) first = bi + __ffs(m) - 1;
                int pos = cnt + __popc(m & ((1u << lane) - 1u));
                if (ok && pos < G2) sel[warp][pos] = i;
                cnt += __popc(m);
                if (cnt >= G2) break;
            }
        }
        for (int p = cnt + lane; p < G2; p += 32) sel[warp][p] = first;
        __syncwarp();
        for (int n = 0; n < G2; n++) {
            int i = sel[warp][n];
            float* row = out + ((((size_t)(b * S2 + s)) * G2) + n) * 131;
            if (lane == 0) {
                row[0] = sx[i] - cx; row[1] = sy[i] - cy; row[2] = sz[i] - cz;
            }
            const float* f = feat + ((size_t)(b * 512) + i) * 128;
            for (int c = lane; c < 128; c += 32) row[3 + c] = f[c];
        }
        __syncwarp();
    }
}

// ---------------- generic fp32 GEMM (small head layers, M=32) ----------------
#define BM 128
#define BN 64
#define BK 16
__global__ void gemm_bias_act(const float* __restrict__ A, const float* __restrict__ W,
                              const float* __restrict__ bias, float* __restrict__ C,
                              int M, int K, int N, int doRelu) {
    __shared__ float As[BK][BM + 4];
    __shared__ float Ws[BK][BN];
    int bm = blockIdx.x * BM, bn = blockIdx.y * BN;
    int tid = threadIdx.x;
    int tx = tid & 15, ty = tid >> 4;
    float acc[8][4] = {};

    for (int k0 = 0; k0 < K; k0 += BK) {
        int lr = tid >> 1, lk0 = (tid & 1) * 8;
        int gm = bm + lr;
#pragma unroll
        for (int i = 0; i < 8; i++) {
            int kk = k0 + lk0 + i;
            As[lk0 + i][lr] = (gm < M && kk < K) ? A[(size_t)gm * K + kk] : 0.0f;
        }
        int ln = tid >> 2, lkw = (tid & 3) * 4;
        int gn = bn + ln;
#pragma unroll
        for (int i = 0; i < 4; i++) {
            int kk = k0 + lkw + i;
            Ws[lkw + i][ln] = (gn < N && kk < K) ? W[(size_t)gn * K + kk] : 0.0f;
        }
        __syncthreads();
#pragma unroll
        for (int k = 0; k < BK; k++) {
            float a[8], bvv[4];
#pragma unroll
            for (int i = 0; i < 8; i++) a[i] = As[k][ty * 8 + i];
#pragma unroll
            for (int j = 0; j < 4; j++) bvv[j] = Ws[k][tx * 4 + j];
#pragma unroll
            for (int i = 0; i < 8; i++)
#pragma unroll
                for (int j = 0; j < 4; j++) acc[i][j] += a[i] * bvv[j];
        }
        __syncthreads();
    }
#pragma unroll
    for (int j = 0; j < 4; j++) {
        int gn = bn + tx * 4 + j;
        if (gn >= N) continue;
        float bv = bias[gn];
#pragma unroll
        for (int i = 0; i < 8; i++) {
            int gm = bm + ty * 8 + i;
            if (gm < M) {
                float v = acc[i][j] + bv;
                if (doRelu) v = fmaxf(v, 0.0f);
                C[(size_t)gm * N + gn] = v;
            }
        }
    }
}

// ---------------- SA3 concat ----------------
__global__ void concat_sa3(const float* __restrict__ cent2, const float* __restrict__ l2p,
                           float* __restrict__ out) {
    int idx = blockIdx.x * blockDim.x + threadIdx.x;
    const int TOT = BATCH * S2 * 259;
    if (idx >= TOT) return;
    int r = idx / 259, c = idx - r * 259;
    out[idx] = (c < 3) ? cent2[r * 3 + c] : l2p[(size_t)r * 256 + (c - 3)];
}

// ---------------- orchestration ----------------
static inline void launch_gemm_simt(const float* A, const float* W, const float* bias, float* C,
                                    int M, int K, int N, int relu) {
    dim3 grid((M + BM - 1) / BM, (N + BN - 1) / BN);
    gemm_bias_act<<<grid, 256>>>(A, W, bias, C, M, K, N, relu);
}
template <int GEN0, int POOLG>
static inline void launch_gemm_tc(const float* A, const float* W, const float* bias, float* C,
                                  int M, int K, int N, int relu,
                                  const float* W0 = nullptr, const float* B0 = nullptr,
                                  const float* GXYZ = nullptr) {
    dim3 grid(M / 128, N / 64);
    gemm_mma<GEN0, POOLG><<<grid, 256>>>(A, W, bias, C, M, K, N, relu, W0, B0, GXYZ);
}

extern "C" void kernel_launch(void* const* d_in, const int* in_sizes, int n_in,
                              void* d_out, int out_size) {
    (void)in_sizes; (void)n_in; (void)out_size;
    const float* xyz  = (const float*)d_in[0];
    const float* s1w0 = (const float*)d_in[1];  const float* s1b0 = (const float*)d_in[2];
    const float* s1w1 = (const float*)d_in[3];  const float* s1b1 = (const float*)d_in[4];
    const float* s1w2 = (const float*)d_in[5];  const float* s1b2 = (const float*)d_in[6];
    const float* s2w0 = (const float*)d_in[7];  const float* s2b0 = (const float*)d_in[8];
    const float* s2w1 = (const float*)d_in[9];  const float* s2b1 = (const float*)d_in[10];
    const float* s2w2 = (const float*)d_in[11]; const float* s2b2 = (const float*)d_in[12];
    const float* s3w0 = (const float*)d_in[13]; const float* s3b0 = (const float*)d_in[14];
    const float* s3w1 = (const float*)d_in[15]; const float* s3b1 = (const float*)d_in[16];
    const float* s3w2 = (const float*)d_in[17]; const float* s3b2 = (const float*)d_in[18];
    const float* f1w  = (const float*)d_in[19]; const float* f1b  = (const float*)d_in[20];
    const float* f2w  = (const float*)d_in[21]; const float* f2b  = (const float*)d_in[22];
    const float* f3w  = (const float*)d_in[23]; const float* f3b  = (const float*)d_in[24];
    float* out = (float*)d_out;

    float *bufA, *bufB, *cent1, *cent2, *l1p, *l2p, *featv;
    int *idx1, *idx2;
    cudaGetSymbolAddress((void**)&bufA, g_bufA);
    cudaGetSymbolAddress((void**)&bufB, g_bufB);
    cudaGetSymbolAddress((void**)&cent1, g_cent1);
    cudaGetSymbolAddress((void**)&cent2, g_cent2);
    cudaGetSymbolAddress((void**)&l1p, g_l1p);
    cudaGetSymbolAddress((void**)&l2p, g_l2p);
    cudaGetSymbolAddress((void**)&featv, g_feat);
    cudaGetSymbolAddress((void**)&idx1, g_idx1);
    cudaGetSymbolAddress((void**)&idx2, g_idx2);

    cudaFuncSetAttribute(bq_group1, cudaFuncAttributeMaxDynamicSharedMemorySize, 3 * N1 * 4);

    const int M1 = BATCH * S1 * G1;   // 524288
    const int M2 = BATCH * S2 * G2;   // 262144
    const int M3 = BATCH * S2;        // 4096

    // ---- SA1 ----
    fps_kernel<8><<<BATCH, 512>>>(xyz, N1, S1, (long)3 * N1, 1, N1, idx1, cent1);
    bq_group1<<<dim3(BATCH, 8), 256, 3 * N1 * 4>>>(xyz, cent1, bufA);
    // layer1 with fused layer0 generation (K=64): bufB = relu(relu(L0(bufA)) @ s1w1^T + b1)
    launch_gemm_tc<1, 0>(nullptr, s1w1, s1b1, bufB, M1, 64, 64, 1, s1w0, s1b0, bufA);
    // layer2 + fused max-pool over G1=32 -> l1p (B*S1, 128)
    launch_gemm_tc<0, 32>(bufB, s1w2, s1b2, l1p, M1, 64, 128, 1);

    // ---- SA2 ----
    fps_kernel<1><<<BATCH, 512>>>(cent1, S1, S2, (long)S1 * 3, 3, 1, idx2, cent2);
    bq_group2<<<dim3(BATCH, 2), 256>>>(cent1, cent2, l1p, bufA);
    launch_gemm_tc<0, 0>(bufA, s2w0, s2b0, bufB, M2, 131, 128, 1);
    launch_gemm_tc<0, 0>(bufB, s2w1, s2b1, bufA, M2, 128, 128, 1);
    // layer2 + fused max-pool over G2=64 -> l2p (B*S2, 256)
    launch_gemm_tc<0, 64>(bufA, s2w2, s2b2, l2p, M2, 128, 256, 1);

    // ---- SA3 (group all) ----
    concat_sa3<<<(M3 * 259 + 255) / 256, 256>>>(cent2, l2p, bufA);
    launch_gemm_tc<0, 0>(bufA, s3w0, s3b0, bufB, M3, 259, 256, 1);
    launch_gemm_tc<0, 0>(bufB, s3w1, s3b1, bufA, M3, 256, 512, 1);
    // layer2 + fused max-pool over all 128 rows -> featv (B, 1024)
    launch_gemm_tc<0, 128>(bufA, s3w2, s3b2, featv, M3, 512, 1024, 1);

    // ---- head (tiny) ----
    launch_gemm_simt(featv, f1w, f1b, bufA, BATCH, 1024, 512, 1);
    launch_gemm_simt(bufA, f2w, f2b, bufB, BATCH, 512, 256, 1);
    launch_gemm_simt(bufB, f3w, f3b, out, BATCH, 256, 6, 0);
}